// round 3
// baseline (speedup 1.0000x reference)
#include <cuda_runtime.h>

#define RES 1024
#define NUM_ROOMS 8
#define N_AGENTS 5000000
#define PLANE (RES * RES)
#define HIST_BLOCKS 4096
#define HIST_THREADS 256

// Scratch (no device allocation allowed)
__device__ __align__(16) float g_ex[NUM_ROOMS * RES];  // exp(-(x_i-cx)^2/(2sx^2))
__device__ __align__(16) float g_ey[NUM_ROOMS * RES];  // exp(-(y_j-cy)^2/(2sy^2))
__device__ int g_maxbits;

// ---------------------------------------------------------------------------
// Kernel 1 (tiny): build separable Gaussian tables, reset max.
// 8192 threads. Flow zeroing is done by cudaMemsetAsync in kernel_launch.
// ---------------------------------------------------------------------------
__global__ void k_tables(const float* __restrict__ rooms) {
    int tid = blockIdx.x * blockDim.x + threadIdx.x;   // < NUM_ROOMS*RES
    int r = tid >> 10, i = tid & (RES - 1);
    float lin = (float)i * (1.0f / (RES - 1));
    float cx = rooms[r * 4 + 0], sx = rooms[r * 4 + 2];
    float cy = rooms[r * 4 + 1], sy = rooms[r * 4 + 3];
    float dx = lin - cx;
    float dy = lin - cy;
    g_ex[tid] = __expf(-dx * dx / (2.0f * sx * sx));
    g_ey[tid] = __expf(-dy * dy / (2.0f * sy * sy));
    if (tid == 0) g_maxbits = 0;
}

// ---------------------------------------------------------------------------
// Kernel 2 (mega): block-role split.
//   blocks [0, RES)            : write 8 layout planes for row i = blockIdx.x
//   blocks [RES, RES+HIST_BLOCKS): grid-stride histogram of agent pairs
// Layout work is small (≈5K LSU-issue cyc/SM total) and hides under the
// histogram's L1tex-wavefront floor (~34K cyc/SM).
// ---------------------------------------------------------------------------
__global__ void __launch_bounds__(HIST_THREADS)
k_mega(const float4* __restrict__ pos4, const float4* __restrict__ wall4,
       float* __restrict__ out, float* __restrict__ flow, int npairs) {
    int bid = blockIdx.x;

    if (bid < RES) {
        // ---- layout role: one row of all 8 planes ----
        int i = bid;
        int q = threadIdx.x;                 // float4 col index 0..255
        int idx4 = (i << 8) + q;
        float4* out4 = (float4*)out;

        float4 w = wall4[idx4];
        w.x = 1.0f - w.x; w.y = 1.0f - w.y; w.z = 1.0f - w.z; w.w = 1.0f - w.w;

        const float4* ey4 = (const float4*)g_ey;
        #pragma unroll
        for (int r = 0; r < NUM_ROOMS; r++) {
            float ex = g_ex[(r << 10) + i];  // uniform per block
            float4 e = ey4[(r << 8) + q];
            float4 o;
            o.x = ex * e.x * w.x;
            o.y = ex * e.y * w.y;
            o.z = ex * e.z * w.z;
            o.w = ex * e.w * w.w;
            out4[r * (PLANE / 4) + idx4] = o;
        }
    } else {
        // ---- histogram role: grid-stride over agent pairs ----
        int stride = HIST_BLOCKS * HIST_THREADS;
        for (int t = (bid - RES) * HIST_THREADS + threadIdx.x; t < npairs; t += stride) {
            float4 p = pos4[t];
            int ix0 = min(max((int)(p.x * (float)RES), 0), RES - 1);
            int iy0 = min(max((int)(p.y * (float)RES), 0), RES - 1);
            int ix1 = min(max((int)(p.z * (float)RES), 0), RES - 1);
            int iy1 = min(max((int)(p.w * (float)RES), 0), RES - 1);
            atomicAdd(&flow[(ix0 << 10) | iy0], 1.0f);
            atomicAdd(&flow[(ix1 << 10) | iy1], 1.0f);
        }
    }
}

// ---------------------------------------------------------------------------
// Kernel 3: global max of flow (grid-stride float4, warp+block reduce,
// int atomicMax — valid since counts >= 0).
// ---------------------------------------------------------------------------
__global__ void k_max(const float4* __restrict__ flow4) {
    __shared__ float smax[8];
    float m = 0.0f;
    int stride = gridDim.x * blockDim.x;
    for (int t = blockIdx.x * blockDim.x + threadIdx.x; t < PLANE / 4; t += stride) {
        float4 v = flow4[t];
        m = fmaxf(m, fmaxf(fmaxf(v.x, v.y), fmaxf(v.z, v.w)));
    }
    #pragma unroll
    for (int off = 16; off > 0; off >>= 1)
        m = fmaxf(m, __shfl_xor_sync(0xffffffffu, m, off));
    int lane = threadIdx.x & 31, warp = threadIdx.x >> 5;
    if (lane == 0) smax[warp] = m;
    __syncthreads();
    if (threadIdx.x == 0) {
        float bm = smax[0];
        #pragma unroll
        for (int w = 1; w < 8; w++) bm = fmaxf(bm, smax[w]);
        atomicMax(&g_maxbits, __float_as_int(bm));
    }
}

// ---------------------------------------------------------------------------
// Kernel 4: normalize flow in place (grid-stride float4).
// ---------------------------------------------------------------------------
__global__ void k_norm(float4* __restrict__ flow4) {
    float inv = 1.0f / (__int_as_float(g_maxbits) + 1e-6f);
    int stride = gridDim.x * blockDim.x;
    for (int t = blockIdx.x * blockDim.x + threadIdx.x; t < PLANE / 4; t += stride) {
        float4 f = flow4[t];
        f.x *= inv; f.y *= inv; f.z *= inv; f.w *= inv;
        flow4[t] = f;
    }
}

// ---------------------------------------------------------------------------
extern "C" void kernel_launch(void* const* d_in, const int* in_sizes, int n_in,
                              void* d_out, int out_size) {
    const float* pos   = (const float*)d_in[0];   // [5000000, 2]
    const float* rooms = (const float*)d_in[1];   // [8, 4]
    const float* wall  = (const float*)d_in[2];   // [1024, 1024]
    float* out = (float*)d_out;                   // 8 planes + flow plane
    float* flow = out + NUM_ROOMS * PLANE;

    // zero flow bins (graph-capturable async memset)
    cudaMemsetAsync(flow, 0, PLANE * sizeof(float));

    // build Gaussian tables (8192 threads)
    k_tables<<<(NUM_ROOMS * RES) / 256, 256>>>(rooms);

    // fused layout + histogram
    int npairs = N_AGENTS / 2;   // 2,500,000 float4 agent pairs
    k_mega<<<RES + HIST_BLOCKS, HIST_THREADS>>>(
        (const float4*)pos, (const float4*)wall, out, flow, npairs);

    // max reduce
    k_max<<<1184, 256>>>((const float4*)flow);

    // normalize flow
    k_norm<<<1184, 256>>>((float4*)flow);
}

// round 4
// speedup vs baseline: 1.1086x; 1.1086x over previous
#include <cuda_runtime.h>

#define RES 1024
#define NUM_ROOMS 8
#define N_AGENTS 5000000
#define PLANE (RES * RES)

// Scratch (no device allocation allowed)
__device__ __align__(16) float g_ex[NUM_ROOMS * RES];  // exp(-(x_i-cx)^2/(2sx^2))
__device__ __align__(16) float g_ey[NUM_ROOMS * RES];  // exp(-(y_j-cy)^2/(2sy^2))
__device__ int g_maxbits;

// ---------------------------------------------------------------------------
// Kernel 1: zero flow (float4) + build Gaussian tables + reset max.
// PLANE/4 threads; first 8192 also build tables.
// ---------------------------------------------------------------------------
__global__ void k_init(const float* __restrict__ rooms, float4* __restrict__ flow4) {
    int tid = blockIdx.x * blockDim.x + threadIdx.x;
    if (tid < PLANE / 4) flow4[tid] = make_float4(0.f, 0.f, 0.f, 0.f);
    if (tid < NUM_ROOMS * RES) {
        int r = tid >> 10, i = tid & (RES - 1);
        float lin = (float)i * (1.0f / (RES - 1));
        float cx = rooms[r * 4 + 0], sx = rooms[r * 4 + 2];
        float cy = rooms[r * 4 + 1], sy = rooms[r * 4 + 3];
        float dx = lin - cx, dy = lin - cy;
        g_ex[tid] = __expf(-dx * dx / (2.0f * sx * sx));
        g_ey[tid] = __expf(-dy * dy / (2.0f * sy * sy));
    }
    if (tid == 0) g_maxbits = 0;
}

// ---------------------------------------------------------------------------
// Kernel 2: histogram. float4 load = 2 agents per thread. Scattered RED.ADD.
// Runs alone — the L2 LTS atomic stream wants no store traffic beside it.
// ---------------------------------------------------------------------------
__global__ void k_hist(const float4* __restrict__ pos4, float* __restrict__ flow, int npairs) {
    int tid = blockIdx.x * blockDim.x + threadIdx.x;
    if (tid >= npairs) return;
    float4 p = pos4[tid];
    int ix0 = min(max((int)(p.x * (float)RES), 0), RES - 1);
    int iy0 = min(max((int)(p.y * (float)RES), 0), RES - 1);
    int ix1 = min(max((int)(p.z * (float)RES), 0), RES - 1);
    int iy1 = min(max((int)(p.w * (float)RES), 0), RES - 1);
    atomicAdd(&flow[(ix0 << 10) | iy0], 1.0f);
    atomicAdd(&flow[(ix1 << 10) | iy1], 1.0f);
}

// ---------------------------------------------------------------------------
// Kernel 3: global max (grid-stride float4, warp+block reduce, int atomicMax).
// ---------------------------------------------------------------------------
__global__ void k_max(const float4* __restrict__ flow4) {
    __shared__ float smax[8];
    float m = 0.0f;
    int stride = gridDim.x * blockDim.x;
    for (int t = blockIdx.x * blockDim.x + threadIdx.x; t < PLANE / 4; t += stride) {
        float4 v = flow4[t];
        m = fmaxf(m, fmaxf(fmaxf(v.x, v.y), fmaxf(v.z, v.w)));
    }
    #pragma unroll
    for (int off = 16; off > 0; off >>= 1)
        m = fmaxf(m, __shfl_xor_sync(0xffffffffu, m, off));
    int lane = threadIdx.x & 31, warp = threadIdx.x >> 5;
    if (lane == 0) smax[warp] = m;
    __syncthreads();
    if (threadIdx.x == 0) {
        float bm = smax[0];
        #pragma unroll
        for (int w = 1; w < 8; w++) bm = fmaxf(bm, smax[w]);
        atomicMax(&g_maxbits, __float_as_int(bm));
    }
}

// ---------------------------------------------------------------------------
// Kernel 4: fused normalize + layout, high-parallelism layout split.
//   blocks [0, 1024)        : normalize one flow row each (float4)
//   blocks [1024, 5120)     : (room-pair rp, row i); each thread writes rooms
//                             rp and rp+4 at one float4 column. 1 wall load,
//                             2 ey loads, 2 STG.128 per thread. 32K warps
//                             total -> latency fully hidden, issue-floor bound.
// ---------------------------------------------------------------------------
__global__ void __launch_bounds__(256) k_final(const float4* __restrict__ wall4,
                                               float* __restrict__ out) {
    float4* out4 = (float4*)out;
    float4* flow4 = out4 + NUM_ROOMS * (PLANE / 4);
    int bid = blockIdx.x;

    if (bid < RES) {
        // normalize flow row
        float inv = 1.0f / (__int_as_float(g_maxbits) + 1e-6f);
        int idx4 = (bid << 8) + threadIdx.x;
        float4 f = flow4[idx4];
        f.x *= inv; f.y *= inv; f.z *= inv; f.w *= inv;
        flow4[idx4] = f;
        return;
    }

    int b = bid - RES;              // 0..4095
    int rp = b >> 10;               // room pair 0..3  (rooms rp, rp+4)
    int i  = b & (RES - 1);         // row
    int q  = threadIdx.x;           // float4 col 0..255
    int idx4 = (i << 8) + q;

    float4 w = wall4[idx4];
    w.x = 1.0f - w.x; w.y = 1.0f - w.y; w.z = 1.0f - w.z; w.w = 1.0f - w.w;

    const float4* ey4 = (const float4*)g_ey;

    int r0 = rp, r1 = rp + 4;
    float ex0 = g_ex[(r0 << 10) + i];
    float ex1 = g_ex[(r1 << 10) + i];
    float4 e0 = ey4[(r0 << 8) + q];
    float4 e1 = ey4[(r1 << 8) + q];

    float4 o0, o1;
    o0.x = ex0 * e0.x * w.x;  o0.y = ex0 * e0.y * w.y;
    o0.z = ex0 * e0.z * w.z;  o0.w = ex0 * e0.w * w.w;
    o1.x = ex1 * e1.x * w.x;  o1.y = ex1 * e1.y * w.y;
    o1.z = ex1 * e1.z * w.z;  o1.w = ex1 * e1.w * w.w;

    out4[r0 * (PLANE / 4) + idx4] = o0;
    out4[r1 * (PLANE / 4) + idx4] = o1;
}

// ---------------------------------------------------------------------------
extern "C" void kernel_launch(void* const* d_in, const int* in_sizes, int n_in,
                              void* d_out, int out_size) {
    const float* pos   = (const float*)d_in[0];   // [5000000, 2]
    const float* rooms = (const float*)d_in[1];   // [8, 4]
    const float* wall  = (const float*)d_in[2];   // [1024, 1024]
    float* out = (float*)d_out;                   // 8 planes + flow plane
    float* flow = out + NUM_ROOMS * PLANE;

    // 1) zero flow + tables
    k_init<<<(PLANE / 4 + 255) / 256, 256>>>(rooms, (float4*)flow);

    // 2) histogram (runs alone; atomic stream owns L2)
    int npairs = N_AGENTS / 2;   // 2,500,000
    k_hist<<<(npairs + 255) / 256, 256>>>((const float4*)pos, flow, npairs);

    // 3) max reduce
    k_max<<<1184, 256>>>((const float4*)flow);

    // 4) fused normalize + layout (high-parallelism split)
    k_final<<<RES + 4 * RES, 256>>>((const float4*)wall, out);
}